// round 1
// baseline (speedup 1.0000x reference)
#include <cuda_runtime.h>
#include <math.h>

// Problem constants
#define PB 2
#define PS 2048
#define PD 1024
#define PH 16
#define PDK 64
// M for projection GEMMs = B*S = 4096, N = K = 1024

// Scratch (device globals; no runtime allocation allowed)
__device__ float g_Q[PB * PH * PS * PDK];
__device__ float g_K[PB * PH * PS * PDK];
__device__ float g_V[PB * PH * PS * PDK];
__device__ float g_O[PB * PH * PS * PDK];
__device__ int g_mask_flag;

// ---------------------------------------------------------------------------
// Mask scan: flag = 1 iff every mask element nonzero (the common case here).
// ---------------------------------------------------------------------------
__global__ void mask_reset_kernel() { g_mask_flag = 1; }

__global__ void mask_scan_kernel(const int4* __restrict__ m, int n4) {
    int idx = blockIdx.x * blockDim.x + threadIdx.x;
    int stride = gridDim.x * blockDim.x;
    bool z = false;
    for (int i = idx; i < n4; i += stride) {
        int4 v = m[i];
        if (!(v.x && v.y && v.z && v.w)) z = true;
    }
    if (z) atomicAnd(&g_mask_flag, 0);
}

// ---------------------------------------------------------------------------
// Projection GEMM: C = A @ W^T with A [4096,1024] row-major, W [1024,1024]
// row-major (so C[m,n] = sum_k A[m,k] * W[n,k] — both K-contiguous, "NT").
// blockIdx.z selects q/k/v input; output written in [b,h,s,dk] layout.
// Tiles 128x128x16, 256 threads, 8x8 per-thread micro-tile.
// ---------------------------------------------------------------------------
__global__ __launch_bounds__(256) void proj_gemm_kernel(
    const float* __restrict__ Aq, const float* __restrict__ Ak,
    const float* __restrict__ Av, const float* __restrict__ W) {
    __shared__ float As[16][132];
    __shared__ float Ws[16][132];

    const float* A = (blockIdx.z == 0) ? Aq : (blockIdx.z == 1) ? Ak : Av;
    float* C = (blockIdx.z == 0) ? g_Q : (blockIdx.z == 1) ? g_K : g_V;

    const int tx = threadIdx.x, ty = threadIdx.y;
    const int tid = ty * 16 + tx;
    const int m0 = blockIdx.y * 128;
    const int n0 = blockIdx.x * 128;
    const int lr = tid >> 2;         // 0..63
    const int lc = (tid & 3) * 4;    // 0,4,8,12

    float acc[8][8];
#pragma unroll
    for (int i = 0; i < 8; i++)
#pragma unroll
        for (int j = 0; j < 8; j++) acc[i][j] = 0.0f;

    for (int k0 = 0; k0 < 1024; k0 += 16) {
#pragma unroll
        for (int r = 0; r < 2; r++) {
            int row = lr + r * 64;
            float4 a = *(const float4*)&A[(m0 + row) * 1024 + k0 + lc];
            As[lc + 0][row] = a.x; As[lc + 1][row] = a.y;
            As[lc + 2][row] = a.z; As[lc + 3][row] = a.w;
            float4 w = *(const float4*)&W[(n0 + row) * 1024 + k0 + lc];
            Ws[lc + 0][row] = w.x; Ws[lc + 1][row] = w.y;
            Ws[lc + 2][row] = w.z; Ws[lc + 3][row] = w.w;
        }
        __syncthreads();
#pragma unroll
        for (int kk = 0; kk < 16; kk++) {
            float a[8], b[8];
#pragma unroll
            for (int i = 0; i < 8; i++) a[i] = As[kk][ty + i * 16];
#pragma unroll
            for (int j = 0; j < 8; j++) b[j] = Ws[kk][tx + j * 16];
#pragma unroll
            for (int i = 0; i < 8; i++)
#pragma unroll
                for (int j = 0; j < 8; j++) acc[i][j] += a[i] * b[j];
        }
        __syncthreads();
    }

    // Store transposed into [b,h,s,dk]
#pragma unroll
    for (int i = 0; i < 8; i++) {
        int m = m0 + ty + i * 16;
        int bb = m >> 11;
        int s = m & 2047;
#pragma unroll
        for (int j = 0; j < 8; j++) {
            int n = n0 + tx + j * 16;
            int h = n >> 6;
            int dk = n & 63;
            C[(((bb << 4) + h) * 2048 + s) * 64 + dk] = acc[i][j];
        }
    }
}

// ---------------------------------------------------------------------------
// Output GEMM: out[m,n] = sum_k O[b,h(k),s,dk(k)] * Wo[n,k]
// ---------------------------------------------------------------------------
__global__ __launch_bounds__(256) void out_gemm_kernel(
    const float* __restrict__ W, float* __restrict__ out) {
    __shared__ float As[16][132];
    __shared__ float Ws[16][132];

    const int tx = threadIdx.x, ty = threadIdx.y;
    const int tid = ty * 16 + tx;
    const int m0 = blockIdx.y * 128;
    const int n0 = blockIdx.x * 128;
    const int lr = tid >> 2;
    const int lc = (tid & 3) * 4;

    float acc[8][8];
#pragma unroll
    for (int i = 0; i < 8; i++)
#pragma unroll
        for (int j = 0; j < 8; j++) acc[i][j] = 0.0f;

    for (int k0 = 0; k0 < 1024; k0 += 16) {
#pragma unroll
        for (int r = 0; r < 2; r++) {
            int row = lr + r * 64;
            int m = m0 + row;
            int bb = m >> 11;
            int s = m & 2047;
            int kg = k0 + lc;
            // A[m, kg..kg+3] = O[b, kg/64, s, kg%64 ..] (contiguous within head)
            float4 a = *(const float4*)&g_O[(((bb << 4) + (kg >> 6)) * 2048 + s) * 64 + (kg & 63)];
            As[lc + 0][row] = a.x; As[lc + 1][row] = a.y;
            As[lc + 2][row] = a.z; As[lc + 3][row] = a.w;
            float4 w = *(const float4*)&W[(n0 + row) * 1024 + k0 + lc];
            Ws[lc + 0][row] = w.x; Ws[lc + 1][row] = w.y;
            Ws[lc + 2][row] = w.z; Ws[lc + 3][row] = w.w;
        }
        __syncthreads();
#pragma unroll
        for (int kk = 0; kk < 16; kk++) {
            float a[8], b[8];
#pragma unroll
            for (int i = 0; i < 8; i++) a[i] = As[kk][ty + i * 16];
#pragma unroll
            for (int j = 0; j < 8; j++) b[j] = Ws[kk][tx + j * 16];
#pragma unroll
            for (int i = 0; i < 8; i++)
#pragma unroll
                for (int j = 0; j < 8; j++) acc[i][j] += a[i] * b[j];
        }
        __syncthreads();
    }

#pragma unroll
    for (int i = 0; i < 8; i++) {
        int m = m0 + ty + i * 16;
#pragma unroll
        for (int j = 0; j < 8; j++) {
            int n = n0 + tx + j * 16;
            out[m * 1024 + n] = acc[i][j];
        }
    }
}

// ---------------------------------------------------------------------------
// Flash attention: block = (b, h, 64 q-rows). Streams over 64-row K/V tiles
// with online softmax. 256 threads as 16x16; 4x4 micro-tiles.
// Smem: Qs[64][64], Ks[64][68], Vs[64][64], Ps[64][64]  (dyn, 66,560 B)
// ---------------------------------------------------------------------------
#define ATTN_SMEM ((64 * 64 + 64 * 68 + 64 * 64 + 64 * 64) * 4)

__global__ __launch_bounds__(256) void attn_kernel(const int* __restrict__ mask) {
    extern __shared__ float sm[];
    float* Qs = sm;                   // [64][64]
    float* Ks = Qs + 64 * 64;         // [64][68]
    float* Vs = Ks + 64 * 68;         // [64][64]
    float* Ps = Vs + 64 * 64;         // [64][64]

    const int tx = threadIdx.x, ty = threadIdx.y;
    const int tid = ty * 16 + tx;
    const int q0 = blockIdx.x * 64;
    const int h = blockIdx.y;
    const int b = blockIdx.z;

    const float* Qg = g_Q + (b * 16 + h) * 2048 * 64;
    const float* Kg = g_K + (b * 16 + h) * 2048 * 64;
    const float* Vg = g_V + (b * 16 + h) * 2048 * 64;
    float* Og = g_O + (b * 16 + h) * 2048 * 64;

    const int lr = tid >> 4;          // 0..15
    const int lc = (tid & 15) * 4;    // 0..60

    // Load Q tile
#pragma unroll
    for (int r = 0; r < 4; r++) {
        int row = lr + r * 16;
        *(float4*)&Qs[row * 64 + lc] = *(const float4*)&Qg[(q0 + row) * 64 + lc];
    }

    float mrow[4], lsum[4], o[4][4];
#pragma unroll
    for (int i = 0; i < 4; i++) {
        mrow[i] = -1e30f;
        lsum[i] = 0.0f;
#pragma unroll
        for (int j = 0; j < 4; j++) o[i][j] = 0.0f;
    }

    const int allones = g_mask_flag;

    for (int kv0 = 0; kv0 < 2048; kv0 += 64) {
        // Load K, V tiles
#pragma unroll
        for (int r = 0; r < 4; r++) {
            int row = lr + r * 16;
            *(float4*)&Ks[row * 68 + lc] = *(const float4*)&Kg[(kv0 + row) * 64 + lc];
            *(float4*)&Vs[row * 64 + lc] = *(const float4*)&Vg[(kv0 + row) * 64 + lc];
        }
        __syncthreads();

        // Scores: s[i][j] = Q[ty*4+i,:] . K[tx*4+j,:]
        float s[4][4];
#pragma unroll
        for (int i = 0; i < 4; i++)
#pragma unroll
            for (int j = 0; j < 4; j++) s[i][j] = 0.0f;

#pragma unroll
        for (int kk = 0; kk < 64; kk += 4) {
            float4 qv[4], kv[4];
#pragma unroll
            for (int i = 0; i < 4; i++) qv[i] = *(const float4*)&Qs[(ty * 4 + i) * 64 + kk];
#pragma unroll
            for (int j = 0; j < 4; j++) kv[j] = *(const float4*)&Ks[(tx * 4 + j) * 68 + kk];
#pragma unroll
            for (int i = 0; i < 4; i++)
#pragma unroll
                for (int j = 0; j < 4; j++) {
                    s[i][j] += qv[i].x * kv[j].x + qv[i].y * kv[j].y +
                               qv[i].z * kv[j].z + qv[i].w * kv[j].w;
                }
        }

#pragma unroll
        for (int i = 0; i < 4; i++)
#pragma unroll
            for (int j = 0; j < 4; j++) s[i][j] *= 0.125f;  // 1/sqrt(64)

        if (!allones) {
#pragma unroll
            for (int i = 0; i < 4; i++)
#pragma unroll
                for (int j = 0; j < 4; j++) {
                    int mi = b * 2048 * 2048 + (q0 + ty * 4 + i) * 2048 + kv0 + tx * 4 + j;
                    if (mask[mi] == 0) s[i][j] = 1e-9f;
                }
        }

        // Online softmax (row groups = 16 consecutive lanes sharing ty)
#pragma unroll
        for (int i = 0; i < 4; i++) {
            float mx = fmaxf(fmaxf(s[i][0], s[i][1]), fmaxf(s[i][2], s[i][3]));
#pragma unroll
            for (int off = 8; off; off >>= 1)
                mx = fmaxf(mx, __shfl_xor_sync(0xffffffffu, mx, off));
            float mnew = fmaxf(mrow[i], mx);
            float corr = __expf(mrow[i] - mnew);
            mrow[i] = mnew;
            float rs = 0.0f;
#pragma unroll
            for (int j = 0; j < 4; j++) {
                s[i][j] = __expf(s[i][j] - mnew);
                rs += s[i][j];
            }
#pragma unroll
            for (int off = 8; off; off >>= 1)
                rs += __shfl_xor_sync(0xffffffffu, rs, off);
            lsum[i] = lsum[i] * corr + rs;
#pragma unroll
            for (int j = 0; j < 4; j++) o[i][j] *= corr;
        }

        // Stage P
#pragma unroll
        for (int i = 0; i < 4; i++) {
            float4 pv = make_float4(s[i][0], s[i][1], s[i][2], s[i][3]);
            *(float4*)&Ps[(ty * 4 + i) * 64 + tx * 4] = pv;
        }
        __syncthreads();

        // O += P @ V
#pragma unroll
        for (int kk = 0; kk < 64; kk++) {
            float4 vv = *(const float4*)&Vs[kk * 64 + tx * 4];
#pragma unroll
            for (int i = 0; i < 4; i++) {
                float p = Ps[(ty * 4 + i) * 64 + kk];
                o[i][0] += p * vv.x;
                o[i][1] += p * vv.y;
                o[i][2] += p * vv.z;
                o[i][3] += p * vv.w;
            }
        }
        __syncthreads();
    }

    // Normalize + store
#pragma unroll
    for (int i = 0; i < 4; i++) {
        float inv = 1.0f / lsum[i];
        float4 r = make_float4(o[i][0] * inv, o[i][1] * inv, o[i][2] * inv, o[i][3] * inv);
        *(float4*)&Og[(q0 + ty * 4 + i) * 64 + tx * 4] = r;
    }
}

// ---------------------------------------------------------------------------
// Launch
// ---------------------------------------------------------------------------
extern "C" void kernel_launch(void* const* d_in, const int* in_sizes, int n_in,
                              void* d_out, int out_size) {
    // metadata order: x, q, k, v, mask, Wq, Wo
    const float* q = (const float*)d_in[1];
    const float* k = (const float*)d_in[2];
    const float* v = (const float*)d_in[3];
    const int* mask = (const int*)d_in[4];
    const float* Wq = (const float*)d_in[5];
    const float* Wo = (const float*)d_in[6];
    float* out = (float*)d_out;

    cudaFuncSetAttribute(attn_kernel, cudaFuncAttributeMaxDynamicSharedMemorySize, ATTN_SMEM);

    mask_reset_kernel<<<1, 1>>>();
    mask_scan_kernel<<<1024, 256>>>((const int4*)mask, PB * PS * PS / 4);

    proj_gemm_kernel<<<dim3(8, 32, 3), dim3(16, 16)>>>(q, k, v, Wq);

    attn_kernel<<<dim3(32, 16, 2), dim3(16, 16), ATTN_SMEM>>>(mask);

    out_gemm_kernel<<<dim3(8, 32, 1), dim3(16, 16)>>>(Wo, out);
}

// round 3
// speedup vs baseline: 2.2375x; 2.2375x over previous
#include <cuda_runtime.h>
#include <cstdint>
#include <math.h>

// Problem constants
#define PB 2
#define PS 2048
#define PD 1024
#define PH 16
#define PDK 64

// Scratch (device globals; no runtime allocation allowed)
__device__ float g_Q[PB * PH * PS * PDK];
__device__ float g_K[PB * PH * PS * PDK];
__device__ float g_V[PB * PH * PS * PDK];
__device__ float g_O[PB * PH * PS * PDK];
__device__ int g_mask_flag;

// ---------------------------------------------------------------------------
// Helpers
// ---------------------------------------------------------------------------
__device__ __forceinline__ uint32_t f2tf32(float f) {
    uint32_t r;
    asm("cvt.rna.tf32.f32 %0, %1;" : "=r"(r) : "f"(f));
    return r;
}

// m16n8k8 tf32 MMA: D = A*B + D. A row-major frag (4 regs), B col-frag (2 regs).
__device__ __forceinline__ void mma8(float* c, const uint32_t* a, uint32_t b0, uint32_t b1) {
    asm volatile(
        "mma.sync.aligned.m16n8k8.row.col.f32.tf32.tf32.f32 "
        "{%0,%1,%2,%3}, {%4,%5,%6,%7}, {%8,%9}, {%0,%1,%2,%3};"
        : "+f"(c[0]), "+f"(c[1]), "+f"(c[2]), "+f"(c[3])
        : "r"(a[0]), "r"(a[1]), "r"(a[2]), "r"(a[3]), "r"(b0), "r"(b1));
}

// ---------------------------------------------------------------------------
// Mask scan
// ---------------------------------------------------------------------------
__global__ void mask_reset_kernel() { g_mask_flag = 1; }

__global__ void mask_scan_kernel(const int4* __restrict__ m, int n4) {
    int idx = blockIdx.x * blockDim.x + threadIdx.x;
    int stride = gridDim.x * blockDim.x;
    bool z = false;
    for (int i = idx; i < n4; i += stride) {
        int4 v = m[i];
        if (!(v.x && v.y && v.z && v.w)) z = true;
    }
    if (z) atomicAnd(&g_mask_flag, 0);
}

// ---------------------------------------------------------------------------
// tf32x3 split GEMM: C = A @ W^T   (error-compensated: ah*bh + ah*bl + al*bh)
// A [4096,1024] K-contig, W [1024,1024] K-contig.
// Block tile 128x128, k-chunk 32. 8 warps as 2(m) x 4(n); warp tile 64x32.
// MODE 0: A = q/k/v by blockIdx.z, C scattered to [b,h,s,dk] (g_Q/g_K/g_V).
// MODE 1: A gathered from g_O ([b,h,s,dk]), C = outp row-major.
// Dynamic SMEM: Ah, Al, Wh, Wl each [128][36] floats = 73728 B.
// ---------------------------------------------------------------------------
#define GEMM_SMEM (4 * 128 * 36 * 4)

template <int MODE>
__global__ __launch_bounds__(256) void gemm_split_kernel(
    const float* __restrict__ Aq, const float* __restrict__ Ak,
    const float* __restrict__ Av, const float* __restrict__ W,
    float* __restrict__ outp) {
    extern __shared__ float sm[];
    float* Ah = sm;
    float* Al = Ah + 128 * 36;
    float* Wh = Al + 128 * 36;
    float* Wl = Wh + 128 * 36;

    const int tid = threadIdx.x;
    const int wid = tid >> 5;
    const int lane = tid & 31;
    const int g = lane >> 2;   // group id 0..7
    const int tig = lane & 3;  // thread in group

    const int n0 = blockIdx.x * 128;
    const int m0 = blockIdx.y * 128;
    const int m0w = (wid & 1) * 64;
    const int n0w = (wid >> 1) * 32;

    const float* A = nullptr;
    float* C = nullptr;
    if (MODE == 0) {
        A = (blockIdx.z == 0) ? Aq : (blockIdx.z == 1) ? Ak : Av;
        C = (blockIdx.z == 0) ? g_Q : (blockIdx.z == 1) ? g_K : g_V;
    } else {
        C = outp;
    }

    float acc[4][4][4];
#pragma unroll
    for (int i = 0; i < 4; i++)
#pragma unroll
        for (int j = 0; j < 4; j++)
#pragma unroll
            for (int r = 0; r < 4; r++) acc[i][j][r] = 0.0f;

    for (int c = 0; c < 32; c++) {
        const int k0 = c * 32;
        // Stage + split 128x32 tiles of A and W.
#pragma unroll
        for (int s2 = 0; s2 < 4; s2++) {
            int slot = tid + s2 * 256;      // 0..1023
            int row = slot >> 3;
            int c4 = (slot & 7) * 4;
            float4 av;
            if (MODE == 0) {
                av = *(const float4*)&A[(m0 + row) * 1024 + k0 + c4];
            } else {
                int m = m0 + row, bb = m >> 11, s = m & 2047;
                av = *(const float4*)&g_O[(((bb << 4) + (k0 >> 6)) * 2048 + s) * 64 +
                                          (k0 & 63) + c4];
            }
            float4 wv = *(const float4*)&W[(n0 + row) * 1024 + k0 + c4];
            float* pa = (float*)&av;
            float* pw = (float*)&wv;
#pragma unroll
            for (int j = 0; j < 4; j++) {
                uint32_t hi = f2tf32(pa[j]);
                Ah[row * 36 + c4 + j] = __uint_as_float(hi);
                Al[row * 36 + c4 + j] =
                    __uint_as_float(f2tf32(pa[j] - __uint_as_float(hi)));
                uint32_t wh = f2tf32(pw[j]);
                Wh[row * 36 + c4 + j] = __uint_as_float(wh);
                Wl[row * 36 + c4 + j] =
                    __uint_as_float(f2tf32(pw[j] - __uint_as_float(wh)));
            }
        }
        __syncthreads();

#pragma unroll
        for (int ks = 0; ks < 4; ks++) {
            const int kk = ks * 8;
            uint32_t ah[4][4], al[4][4];
#pragma unroll
            for (int mf = 0; mf < 4; mf++) {
                int r0 = (m0w + mf * 16 + g) * 36;
                int r1 = (m0w + mf * 16 + g + 8) * 36;
                ah[mf][0] = __float_as_uint(Ah[r0 + kk + tig]);
                ah[mf][1] = __float_as_uint(Ah[r1 + kk + tig]);
                ah[mf][2] = __float_as_uint(Ah[r0 + kk + tig + 4]);
                ah[mf][3] = __float_as_uint(Ah[r1 + kk + tig + 4]);
                al[mf][0] = __float_as_uint(Al[r0 + kk + tig]);
                al[mf][1] = __float_as_uint(Al[r1 + kk + tig]);
                al[mf][2] = __float_as_uint(Al[r0 + kk + tig + 4]);
                al[mf][3] = __float_as_uint(Al[r1 + kk + tig + 4]);
            }
#pragma unroll
            for (int nf = 0; nf < 4; nf++) {
                int rn = (n0w + nf * 8 + g) * 36;
                uint32_t bh0 = __float_as_uint(Wh[rn + kk + tig]);
                uint32_t bh1 = __float_as_uint(Wh[rn + kk + tig + 4]);
                uint32_t bl0 = __float_as_uint(Wl[rn + kk + tig]);
                uint32_t bl1 = __float_as_uint(Wl[rn + kk + tig + 4]);
#pragma unroll
                for (int mf = 0; mf < 4; mf++) {
                    mma8(acc[mf][nf], ah[mf], bh0, bh1);   // hi*hi
                    mma8(acc[mf][nf], ah[mf], bl0, bl1);   // hi*lo
                    mma8(acc[mf][nf], al[mf], bh0, bh1);   // lo*hi
                }
            }
        }
        __syncthreads();
    }

    // Epilogue: float2 per (c0,c1)/(c2,c3) pair.
#pragma unroll
    for (int mf = 0; mf < 4; mf++) {
#pragma unroll
        for (int nf = 0; nf < 4; nf++) {
            int col = n0 + n0w + nf * 8 + 2 * tig;
            int row0 = m0 + m0w + mf * 16 + g;
            int row1 = row0 + 8;
            if (MODE == 0) {
                int h = col >> 6, dk = col & 63;
                int bb0 = row0 >> 11, s0 = row0 & 2047;
                int bb1 = row1 >> 11, s1 = row1 & 2047;
                *(float2*)&C[(((bb0 << 4) + h) * 2048 + s0) * 64 + dk] =
                    make_float2(acc[mf][nf][0], acc[mf][nf][1]);
                *(float2*)&C[(((bb1 << 4) + h) * 2048 + s1) * 64 + dk] =
                    make_float2(acc[mf][nf][2], acc[mf][nf][3]);
            } else {
                *(float2*)&C[row0 * 1024 + col] =
                    make_float2(acc[mf][nf][0], acc[mf][nf][1]);
                *(float2*)&C[row1 * 1024 + col] =
                    make_float2(acc[mf][nf][2], acc[mf][nf][3]);
            }
        }
    }
}

// ---------------------------------------------------------------------------
// Flash attention with tf32 HMMA.
// Block: 64 q-rows, 4 warps (128 thr); each warp owns 16 q-rows.
// KV tiles of 64. S and P in register fragments; P staged via SMEM for PV mma.
// SMEM (dyn): Qs/Ks/Vs/Ps each [64][68] floats = 69632 B.
// ---------------------------------------------------------------------------
#define ATTN_SMEM (4 * 64 * 68 * 4)

__global__ __launch_bounds__(128) void attn_kernel(const int* __restrict__ mask) {
    extern __shared__ float sm[];
    float* Qs = sm;                  // [64][68] tf32 bits
    float* Ks = Qs + 64 * 68;
    float* Vs = Ks + 64 * 68;
    float* Ps = Vs + 64 * 68;

    const int tid = threadIdx.x;
    const int w = tid >> 5;
    const int lane = tid & 31;
    const int g = lane >> 2;
    const int tig = lane & 3;

    const int q0 = blockIdx.x * 64;
    const int h = blockIdx.y;
    const int b = blockIdx.z;

    const float* Qg = g_Q + (b * 16 + h) * 2048 * 64;
    const float* Kg = g_K + (b * 16 + h) * 2048 * 64;
    const float* Vg = g_V + (b * 16 + h) * 2048 * 64;
    float* Og = g_O + (b * 16 + h) * 2048 * 64;

    // Load Q tile (tf32-converted)
#pragma unroll
    for (int i = 0; i < 8; i++) {
        int slot = tid + i * 128;     // 0..1023
        int row = slot >> 4;
        int c4 = (slot & 15) * 4;
        float4 qv = *(const float4*)&Qg[(q0 + row) * 64 + c4];
        Qs[row * 68 + c4 + 0] = __uint_as_float(f2tf32(qv.x));
        Qs[row * 68 + c4 + 1] = __uint_as_float(f2tf32(qv.y));
        Qs[row * 68 + c4 + 2] = __uint_as_float(f2tf32(qv.z));
        Qs[row * 68 + c4 + 3] = __uint_as_float(f2tf32(qv.w));
    }

    float o[8][4];
#pragma unroll
    for (int nf = 0; nf < 8; nf++)
#pragma unroll
        for (int r = 0; r < 4; r++) o[nf][r] = 0.0f;
    float mprev0 = -1e30f, mprev1 = -1e30f;
    float l0 = 0.0f, l1 = 0.0f;

    const int allones = g_mask_flag;
    const int rowl0 = w * 16 + g;      // warp-local row within the 64-row tile
    const int rowl1 = rowl0 + 8;

    for (int kv0 = 0; kv0 < 2048; kv0 += 64) {
        // Load K, V tiles (tf32-converted)
#pragma unroll
        for (int i = 0; i < 8; i++) {
            int slot = tid + i * 128;
            int row = slot >> 4;
            int c4 = (slot & 15) * 4;
            float4 kv = *(const float4*)&Kg[(kv0 + row) * 64 + c4];
            float4 vv = *(const float4*)&Vg[(kv0 + row) * 64 + c4];
            Ks[row * 68 + c4 + 0] = __uint_as_float(f2tf32(kv.x));
            Ks[row * 68 + c4 + 1] = __uint_as_float(f2tf32(kv.y));
            Ks[row * 68 + c4 + 2] = __uint_as_float(f2tf32(kv.z));
            Ks[row * 68 + c4 + 3] = __uint_as_float(f2tf32(kv.w));
            Vs[row * 68 + c4 + 0] = __uint_as_float(f2tf32(vv.x));
            Vs[row * 68 + c4 + 1] = __uint_as_float(f2tf32(vv.y));
            Vs[row * 68 + c4 + 2] = __uint_as_float(f2tf32(vv.z));
            Vs[row * 68 + c4 + 3] = __uint_as_float(f2tf32(vv.w));
        }
        __syncthreads();

        // S = Q @ K^T  (s[nf] covers kv cols nf*8..nf*8+7)
        float s[8][4];
#pragma unroll
        for (int nf = 0; nf < 8; nf++)
#pragma unroll
            for (int r = 0; r < 4; r++) s[nf][r] = 0.0f;

#pragma unroll
        for (int ks = 0; ks < 8; ks++) {
            const int kk = ks * 8;
            uint32_t a[4];
            a[0] = __float_as_uint(Qs[rowl0 * 68 + kk + tig]);
            a[1] = __float_as_uint(Qs[rowl1 * 68 + kk + tig]);
            a[2] = __float_as_uint(Qs[rowl0 * 68 + kk + tig + 4]);
            a[3] = __float_as_uint(Qs[rowl1 * 68 + kk + tig + 4]);
#pragma unroll
            for (int nf = 0; nf < 8; nf++) {
                int rn = (nf * 8 + g) * 68;
                uint32_t b0 = __float_as_uint(Ks[rn + kk + tig]);
                uint32_t b1 = __float_as_uint(Ks[rn + kk + tig + 4]);
                mma8(s[nf], a, b0, b1);
            }
        }

#pragma unroll
        for (int nf = 0; nf < 8; nf++)
#pragma unroll
            for (int r = 0; r < 4; r++) s[nf][r] *= 0.125f;

        if (!allones) {
            int qr0 = q0 + rowl0, qr1 = q0 + rowl1;
#pragma unroll
            for (int nf = 0; nf < 8; nf++) {
                int kc = kv0 + nf * 8 + 2 * tig;
                const int* mb = mask + (long long)b * 2048 * 2048;
                if (mb[qr0 * 2048 + kc] == 0) s[nf][0] = 1e-9f;
                if (mb[qr0 * 2048 + kc + 1] == 0) s[nf][1] = 1e-9f;
                if (mb[qr1 * 2048 + kc] == 0) s[nf][2] = 1e-9f;
                if (mb[qr1 * 2048 + kc + 1] == 0) s[nf][3] = 1e-9f;
            }
        }

        // Online softmax over the two rows owned by this thread's group.
        float mx0 = -1e30f, mx1 = -1e30f;
#pragma unroll
        for (int nf = 0; nf < 8; nf++) {
            mx0 = fmaxf(mx0, fmaxf(s[nf][0], s[nf][1]));
            mx1 = fmaxf(mx1, fmaxf(s[nf][2], s[nf][3]));
        }
        mx0 = fmaxf(mx0, __shfl_xor_sync(0xffffffffu, mx0, 1));
        mx0 = fmaxf(mx0, __shfl_xor_sync(0xffffffffu, mx0, 2));
        mx1 = fmaxf(mx1, __shfl_xor_sync(0xffffffffu, mx1, 1));
        mx1 = fmaxf(mx1, __shfl_xor_sync(0xffffffffu, mx1, 2));

        float mnew0 = fmaxf(mprev0, mx0), mnew1 = fmaxf(mprev1, mx1);
        float corr0 = __expf(mprev0 - mnew0), corr1 = __expf(mprev1 - mnew1);
        mprev0 = mnew0; mprev1 = mnew1;

        float rs0 = 0.0f, rs1 = 0.0f;
#pragma unroll
        for (int nf = 0; nf < 8; nf++) {
            s[nf][0] = __expf(s[nf][0] - mnew0);
            s[nf][1] = __expf(s[nf][1] - mnew0);
            s[nf][2] = __expf(s[nf][2] - mnew1);
            s[nf][3] = __expf(s[nf][3] - mnew1);
            rs0 += s[nf][0] + s[nf][1];
            rs1 += s[nf][2] + s[nf][3];
        }
        rs0 += __shfl_xor_sync(0xffffffffu, rs0, 1);
        rs0 += __shfl_xor_sync(0xffffffffu, rs0, 2);
        rs1 += __shfl_xor_sync(0xffffffffu, rs1, 1);
        rs1 += __shfl_xor_sync(0xffffffffu, rs1, 2);
        l0 = l0 * corr0 + rs0;
        l1 = l1 * corr1 + rs1;

#pragma unroll
        for (int nf = 0; nf < 8; nf++) {
            o[nf][0] *= corr0; o[nf][1] *= corr0;
            o[nf][2] *= corr1; o[nf][3] *= corr1;
        }

        // Stage P (tf32-converted)
#pragma unroll
        for (int nf = 0; nf < 8; nf++) {
            int pc = nf * 8 + 2 * tig;
            *(uint2*)&Ps[rowl0 * 68 + pc] =
                make_uint2(f2tf32(s[nf][0]), f2tf32(s[nf][1]));
            *(uint2*)&Ps[rowl1 * 68 + pc] =
                make_uint2(f2tf32(s[nf][2]), f2tf32(s[nf][3]));
        }
        __syncthreads();

        // O += P @ V   (contraction over kv=64; o[nf] covers dk cols nf*8..+7)
#pragma unroll
        for (int ks = 0; ks < 8; ks++) {
            const int kk = ks * 8;
            uint32_t a[4];
            a[0] = __float_as_uint(Ps[rowl0 * 68 + kk + tig]);
            a[1] = __float_as_uint(Ps[rowl1 * 68 + kk + tig]);
            a[2] = __float_as_uint(Ps[rowl0 * 68 + kk + tig + 4]);
            a[3] = __float_as_uint(Ps[rowl1 * 68 + kk + tig + 4]);
#pragma unroll
            for (int nf = 0; nf < 8; nf++) {
                uint32_t b0 = __float_as_uint(Vs[(kk + tig) * 68 + nf * 8 + g]);
                uint32_t b1 = __float_as_uint(Vs[(kk + tig + 4) * 68 + nf * 8 + g]);
                mma8(o[nf], a, b0, b1);
            }
        }
        __syncthreads();
    }

    // Normalize + store
    float inv0 = 1.0f / l0, inv1 = 1.0f / l1;
#pragma unroll
    for (int nf = 0; nf < 8; nf++) {
        int col = nf * 8 + 2 * tig;
        *(float2*)&Og[(q0 + rowl0) * 64 + col] =
            make_float2(o[nf][0] * inv0, o[nf][1] * inv0);
        *(float2*)&Og[(q0 + rowl1) * 64 + col] =
            make_float2(o[nf][2] * inv1, o[nf][3] * inv1);
    }
}

// ---------------------------------------------------------------------------
// Launch
// ---------------------------------------------------------------------------
extern "C" void kernel_launch(void* const* d_in, const int* in_sizes, int n_in,
                              void* d_out, int out_size) {
    // metadata order: x, q, k, v, mask, Wq, Wo
    const float* q = (const float*)d_in[1];
    const float* k = (const float*)d_in[2];
    const float* v = (const float*)d_in[3];
    const int* mask = (const int*)d_in[4];
    const float* Wq = (const float*)d_in[5];
    const float* Wo = (const float*)d_in[6];
    float* out = (float*)d_out;

    cudaFuncSetAttribute(attn_kernel, cudaFuncAttributeMaxDynamicSharedMemorySize, ATTN_SMEM);
    cudaFuncSetAttribute(gemm_split_kernel<0>, cudaFuncAttributeMaxDynamicSharedMemorySize, GEMM_SMEM);
    cudaFuncSetAttribute(gemm_split_kernel<1>, cudaFuncAttributeMaxDynamicSharedMemorySize, GEMM_SMEM);

    mask_reset_kernel<<<1, 1>>>();
    mask_scan_kernel<<<1024, 256>>>((const int4*)mask, PB * PS * PS / 4);

    gemm_split_kernel<0><<<dim3(8, 32, 3), 256, GEMM_SMEM>>>(q, k, v, Wq, nullptr);

    attn_kernel<<<dim3(32, 16, 2), 128, ATTN_SMEM>>>(mask);

    gemm_split_kernel<1><<<dim3(8, 32, 1), 256, GEMM_SMEM>>>(nullptr, nullptr, nullptr, Wo, out);
}

// round 5
// speedup vs baseline: 3.7082x; 1.6573x over previous
#include <cuda_runtime.h>
#include <cuda_bf16.h>
#include <cstdint>
#include <math.h>

#define PB 2
#define PS 2048
#define PD 1024
#define PH 16
#define PDK 64

__device__ float g_Q[PB * PH * PS * PDK];
__device__ float g_K[PB * PH * PS * PDK];
__device__ float g_V[PB * PH * PS * PDK];
__device__ int g_mask_flag;

__device__ __nv_bfloat16 g_Ah[3 * 4096 * 1024];
__device__ __nv_bfloat16 g_Al[3 * 4096 * 1024];
__device__ __nv_bfloat16 g_Wqh[1024 * 1024];
__device__ __nv_bfloat16 g_Wql[1024 * 1024];
__device__ __nv_bfloat16 g_Woh[1024 * 1024];
__device__ __nv_bfloat16 g_Wol[1024 * 1024];
__device__ __nv_bfloat16 g_Oh[4096 * 1024];
__device__ __nv_bfloat16 g_Ol[4096 * 1024];

__device__ __forceinline__ uint32_t smem_u32(const void* p) {
    uint32_t a;
    asm("{ .reg .u64 t; cvta.to.shared.u64 t, %1; cvt.u32.u64 %0, t; }"
        : "=r"(a) : "l"(p));
    return a;
}

__device__ __forceinline__ uint32_t f2tf32(float f) {
    uint32_t r;
    asm("cvt.rna.tf32.f32 %0, %1;" : "=r"(r) : "f"(f));
    return r;
}

__device__ __forceinline__ void mma8(float* c, const uint32_t* a, uint32_t b0, uint32_t b1) {
    asm volatile(
        "mma.sync.aligned.m16n8k8.row.col.f32.tf32.tf32.f32 "
        "{%0,%1,%2,%3}, {%4,%5,%6,%7}, {%8,%9}, {%0,%1,%2,%3};"
        : "+f"(c[0]), "+f"(c[1]), "+f"(c[2]), "+f"(c[3])
        : "r"(a[0]), "r"(a[1]), "r"(a[2]), "r"(a[3]), "r"(b0), "r"(b1));
}

__device__ __forceinline__ void mma16(float* c, const uint32_t* a, uint32_t b0, uint32_t b1) {
    asm volatile(
        "mma.sync.aligned.m16n8k16.row.col.f32.bf16.bf16.f32 "
        "{%0,%1,%2,%3}, {%4,%5,%6,%7}, {%8,%9}, {%0,%1,%2,%3};"
        : "+f"(c[0]), "+f"(c[1]), "+f"(c[2]), "+f"(c[3])
        : "r"(a[0]), "r"(a[1]), "r"(a[2]), "r"(a[3]), "r"(b0), "r"(b1));
}

#define CP16(dst_u32, src_ptr) \
    asm volatile("cp.async.cg.shared.global [%0], [%1], 16;" :: "r"(dst_u32), "l"(src_ptr))
#define CP_COMMIT() asm volatile("cp.async.commit_group;" ::: "memory")
#define CP_WAIT0() asm volatile("cp.async.wait_group 0;" ::: "memory")

__global__ void mask_reset_kernel() { g_mask_flag = 1; }

__global__ void mask_scan_kernel(const int4* __restrict__ m, int n4) {
    int idx = blockIdx.x * blockDim.x + threadIdx.x;
    int stride = gridDim.x * blockDim.x;
    bool z = false;
    for (int i = idx; i < n4; i += stride) {
        int4 v = m[i];
        if (!(v.x && v.y && v.z && v.w)) z = true;
    }
    if (z) atomicAnd(&g_mask_flag, 0);
}

__global__ void split_pair_kernel(const float* __restrict__ src,
                                  __nv_bfloat16* __restrict__ hi,
                                  __nv_bfloat16* __restrict__ lo, int n2) {
    int i = blockIdx.x * blockDim.x + threadIdx.x;
    int stride = gridDim.x * blockDim.x;
    for (; i < n2; i += stride) {
        float2 f = ((const float2*)src)[i];
        __nv_bfloat162 h = __floats2bfloat162_rn(f.x, f.y);
        float hx = __bfloat162float(h.x), hy = __bfloat162float(h.y);
        __nv_bfloat162 l = __floats2bfloat162_rn(f.x - hx, f.y - hy);
        ((__nv_bfloat162*)hi)[i] = h;
        ((__nv_bfloat162*)lo)[i] = l;
    }
}

#define GEMM_SMEM (4 * 128 * 36 * 4)

template <int MODE>
__global__ __launch_bounds__(256, 2) void gemm_bf16_kernel(
    const __nv_bfloat16* __restrict__ AhG, const __nv_bfloat16* __restrict__ AlG,
    const __nv_bfloat16* __restrict__ WhG, const __nv_bfloat16* __restrict__ WlG,
    float* __restrict__ outp) {
    extern __shared__ uint32_t smu[];
    uint32_t* Ah = smu;
    uint32_t* Al = Ah + 128 * 36;
    uint32_t* Wh = Al + 128 * 36;
    uint32_t* Wl = Wh + 128 * 36;
    const uint32_t sAh = smem_u32(Ah), sAl = smem_u32(Al);
    const uint32_t sWh = smem_u32(Wh), sWl = smem_u32(Wl);

    const int tid = threadIdx.x;
    const int wid = tid >> 5;
    const int lane = tid & 31;
    const int g = lane >> 2;
    const int tig = lane & 3;

    const int n0 = blockIdx.x * 128;
    const int m0 = blockIdx.y * 128;
    const int m0w = (wid & 1) * 64;
    const int n0w = (wid >> 1) * 32;

    float* C;
    if (MODE == 0) {
        C = (blockIdx.z == 0) ? g_Q : (blockIdx.z == 1) ? g_K : g_V;
    } else {
        C = outp;
    }
    const int zoff = (MODE == 0) ? (int)blockIdx.z * 4096 * 1024 : 0;

    int offA[4], offW[4];
    uint32_t sdst[4];
#pragma unroll
    for (int i = 0; i < 4; i++) {
        int slot = tid + i * 256;
        int row = slot >> 3;
        int seg = slot & 7;
        sdst[i] = (uint32_t)(row * 36 + seg * 4) * 4;
        offW[i] = (n0 + row) * 1024 + seg * 8;
        if (MODE == 0) {
            offA[i] = zoff + (m0 + row) * 1024 + seg * 8;
        } else {
            int m = m0 + row, bb = m >> 11, s = m & 2047;
            offA[i] = ((bb * 16) * 2048 + s) * 64 + seg * 8;
        }
    }
    const int dA = (MODE == 0) ? 64 : (2048 * 64);

    float acc[4][4][4];
#pragma unroll
    for (int i = 0; i < 4; i++)
#pragma unroll
        for (int j = 0; j < 4; j++)
#pragma unroll
            for (int r = 0; r < 4; r++) acc[i][j][r] = 0.0f;

    for (int c = 0; c < 16; c++) {
#pragma unroll
        for (int i = 0; i < 4; i++) {
            CP16(sAh + sdst[i], AhG + offA[i] + c * dA);
            CP16(sAl + sdst[i], AlG + offA[i] + c * dA);
            CP16(sWh + sdst[i], WhG + offW[i] + c * 64);
            CP16(sWl + sdst[i], WlG + offW[i] + c * 64);
        }
        CP_COMMIT();
        CP_WAIT0();
        __syncthreads();

#pragma unroll
        for (int ks = 0; ks < 4; ks++) {
            const int kk = ks * 8;
            uint32_t ah[4][4], alr[4][4];
#pragma unroll
            for (int mf = 0; mf < 4; mf++) {
                int r0 = (m0w + mf * 16 + g) * 36 + kk;
                int r1 = r0 + 8 * 36;
                ah[mf][0] = Ah[r0 + tig];
                ah[mf][1] = Ah[r1 + tig];
                ah[mf][2] = Ah[r0 + tig + 4];
                ah[mf][3] = Ah[r1 + tig + 4];
                alr[mf][0] = Al[r0 + tig];
                alr[mf][1] = Al[r1 + tig];
                alr[mf][2] = Al[r0 + tig + 4];
                alr[mf][3] = Al[r1 + tig + 4];
            }
#pragma unroll
            for (int nf = 0; nf < 4; nf++) {
                int rn = (n0w + nf * 8 + g) * 36 + kk;
                uint32_t bh0 = Wh[rn + tig], bh1 = Wh[rn + tig + 4];
                uint32_t bl0 = Wl[rn + tig], bl1 = Wl[rn + tig + 4];
#pragma unroll
                for (int mf = 0; mf < 4; mf++) {
                    mma16(acc[mf][nf], ah[mf], bh0, bh1);
                    mma16(acc[mf][nf], ah[mf], bl0, bl1);
                    mma16(acc[mf][nf], alr[mf], bh0, bh1);
                }
            }
        }
        __syncthreads();
    }

#pragma unroll
    for (int mf = 0; mf < 4; mf++) {
#pragma unroll
        for (int nf = 0; nf < 4; nf++) {
            int col = n0 + n0w + nf * 8 + 2 * tig;
            int row0 = m0 + m0w + mf * 16 + g;
            int row1 = row0 + 8;
            if (MODE == 0) {
                int h = col >> 6, dk = col & 63;
                int bb0 = row0 >> 11, s0 = row0 & 2047;
                int bb1 = row1 >> 11, s1 = row1 & 2047;
                *(float2*)&C[(((bb0 << 4) + h) * 2048 + s0) * 64 + dk] =
                    make_float2(acc[mf][nf][0], acc[mf][nf][1]);
                *(float2*)&C[(((bb1 << 4) + h) * 2048 + s1) * 64 + dk] =
                    make_float2(acc[mf][nf][2], acc[mf][nf][3]);
            } else {
                *(float2*)&C[row0 * 1024 + col] =
                    make_float2(acc[mf][nf][0], acc[mf][nf][1]);
                *(float2*)&C[row1 * 1024 + col] =
                    make_float2(acc[mf][nf][2], acc[mf][nf][3]);
            }
        }
    }
}

#define ATTN_SMEM ((64 * 68 * 2 + 64 * 72) * 4)

__global__ __launch_bounds__(128, 4) void attn_kernel(const int* __restrict__ mask) {
    extern __shared__ float sm[];
    float* Qs = sm;
    float* Ks = Qs + 64 * 68;
    float* Vs = Ks + 64 * 68;
    float* Ps = Ks;

    const int tid = threadIdx.x;
    const int w = tid >> 5;
    const int lane = tid & 31;
    const int g = lane >> 2;
    const int tig = lane & 3;

    const int q0 = blockIdx.x * 64;
    const int h = blockIdx.y;
    const int b = blockIdx.z;

    const float* Qg = g_Q + (b * 16 + h) * 2048 * 64;
    const float* Kg = g_K + (b * 16 + h) * 2048 * 64;
    const float* Vg = g_V + (b * 16 + h) * 2048 * 64;

#pragma unroll
    for (int i = 0; i < 8; i++) {
        int slot = tid + i * 128;
        int row = slot >> 4;
        int c4 = (slot & 15) * 4;
        float4 qv = *(const float4*)&Qg[(q0 + row) * 64 + c4];
        Qs[row * 68 + c4 + 0] = __uint_as_float(f2tf32(qv.x));
        Qs[row * 68 + c4 + 1] = __uint_as_float(f2tf32(qv.y));
        Qs[row * 68 + c4 + 2] = __uint_as_float(f2tf32(qv.z));
        Qs[row * 68 + c4 + 3] = __uint_as_float(f2tf32(qv.w));
    }

    float o[8][4];
#pragma unroll
    for (int nf = 0; nf < 8; nf++)
#pragma unroll
        for (int r = 0; r < 4; r++) o[nf][r] = 0.0f;
    float mprev0 = -1e30f, mprev1 = -1e30f;
    float l0 = 0.0f, l1 = 0.0f;

    const int allones = g_mask_flag;
    const int rowl0 = w * 16 + g;
    const int rowl1 = rowl0 + 8;

    for (int kv0 = 0; kv0 < 2048; kv0 += 64) {
#pragma unroll
        for (int i = 0; i < 8; i++) {
            int slot = tid + i * 128;
            int row = slot >> 4;
            int c4 = (slot & 15) * 4;
            float4 kv = *(const float4*)&Kg[(kv0 + row) * 64 + c4];
            float4 vv = *(const float4*)&Vg[(kv0 + row) * 64 + c4];
            Ks[row * 68 + c4 + 0] = __uint_as_float(f2tf32(kv.x));
            Ks[row * 68 + c4 + 1] = __uint_as_float(f2tf32(kv.y));
            Ks[row * 68 + c4 + 2] = __uint_as_float(f2tf32(kv.z));
            Ks[row * 68 + c4 + 3] = __uint_as_float(f2tf32(kv.w));
            Vs[row * 72 + c4 + 0] = __uint_as_float(f2tf32(vv.x));
            Vs[row * 72 + c4 + 1] = __uint_as_float(f2tf32(vv.y));
            Vs[row * 72 + c4 + 2] = __uint_as_float(f2tf32(vv.z));
            Vs[row * 72 + c4 + 3] = __uint_as_float(f2tf32(vv.w));
        }
        __syncthreads();

        float s[8][4];
#pragma unroll
        for (int nf = 0; nf < 8; nf++)
#pragma unroll
            for (int r = 0; r < 4; r++) s[nf][r] = 0.0f;

#pragma unroll
        for (int ks = 0; ks < 8; ks++) {
            const int kk = ks * 8;
            uint32_t a[4];
            a[0] = __float_as_uint(Qs[rowl0 * 68 + kk + tig]);
            a[1] = __float_as_uint(Qs[rowl1 * 68 + kk + tig]);
            a[2] = __float_as_uint(Qs[rowl0 * 68 + kk + tig + 4]);
            a[3] = __float_as_uint(Qs[rowl1 * 68 + kk + tig + 4]);
#pragma unroll
            for (int nf = 0; nf < 8; nf++) {
                int rn = (nf * 8 + g) * 68;
                uint32_t b0 = __float_as_uint(Ks[rn + kk + tig]);
                uint32_t b1 = __float_as_uint(Ks[rn + kk + tig + 4]);
                mma8(s[nf], a, b0, b1);
            }
        }
        __syncthreads();

#pragma unroll
        for (int nf = 0; nf < 8; nf++)
#pragma unroll
            for (int r = 0; r < 4; r++) s[nf][r] *= 0.125f;

        if (!allones) {
            int qr0 = q0 + rowl0, qr1 = q0 + rowl1;
            const int* mb = mask + (long long)b * 2048 * 2048;
#pragma unroll
            for (int nf = 0; nf < 8; nf++) {
                int kc = kv0 + nf * 8 + 2 * tig;
                if (mb[qr0 * 2048 + kc] == 0) s[nf][0] = 1e-9f;
                if (mb[qr0 * 2048 + kc + 1] == 0) s[nf][1] = 1e-9f;
                if (mb[qr1 * 2048 + kc] == 0) s[nf][2] = 1e-9f;
                if (mb[qr1 * 2048 + kc + 1] == 0) s[nf][3] = 1e-9f;
            }
        }

        float mx0 = -1e30f, mx1 = -1e30f;
#pragma unroll
        for (int nf = 0; nf < 8; nf++) {
            mx0 = fmaxf(mx0, fmaxf(s[nf][0], s[nf][1]));
            mx1 = fmaxf(mx1, fmaxf(s[nf][2], s[nf][3]));
        }
        mx0 = fmaxf(mx0, __shfl_xor_sync(0xffffffffu, mx0, 1));
        mx0 = fmaxf(mx0, __shfl_xor_sync(0xffffffffu, mx0, 2));
        mx1 = fmaxf(mx1, __shfl_xor_sync(0xffffffffu, mx1, 1));
        mx1 = fmaxf(mx1, __shfl_xor_sync(0xffffffffu, mx1, 2));

        float mnew0 = fmaxf(mprev0, mx0), mnew1 = fmaxf(mprev1, mx1);
        float corr0 = __expf(mprev0 - mnew0), corr1 = __expf(mprev1 - mnew1);
        mprev0 = mnew0; mprev1 = mnew1;

        float rs0 = 0.0f, rs1 = 0.0f;
#pragma unroll
        for (int nf = 0; nf < 8; nf++) {
            s[nf][0] = __expf(s[nf][0] - mnew0);
            s[nf][1] = __expf(s[nf][1] - mnew0);
            s[nf][2] = __expf(s[nf][2] - mnew1);
            s[nf][3] = __expf(s[nf][3] - mnew1);
            rs0 += s[nf][0] + s[nf][1];
            rs1 += s[nf][2] + s[nf][3];
        }
        rs0 += __shfl_xor_sync(0xffffffffu, rs0, 1);
        rs0 += __shfl_xor_sync(0xffffffffu, rs0, 2);
        rs1 += __shfl_xor_sync(0xffffffffu, rs1, 1);
        rs1 += __shfl_xor_sync(0xffffffffu, rs1, 2);
        l0 = l0 * corr0 + rs0;
        l1 = l1 * corr1 + rs1;

#pragma unroll
        for (int nf = 0; nf < 8; nf++) {
            o[nf][0] *= corr0; o[nf][1] *= corr0;
            o[nf][2] *= corr1; o[nf][3] *= corr1;
        }

#pragma unroll
        for (int nf = 0; nf < 8; nf++) {
            int pc = nf * 8 + 2 * tig;
            *(uint2*)&Ps[rowl0 * 68 + pc] =
                make_uint2(f2tf32(s[nf][0]), f2tf32(s[nf][1]));
            *(uint2*)&Ps[rowl1 * 68 + pc] =
                make_uint2(f2tf32(s[nf][2]), f2tf32(s[nf][3]));
        }
        __syncthreads();

#pragma unroll
        for (int ks = 0; ks < 8; ks++) {
            const int kk = ks * 8;
            uint32_t a[4];
            a[0] = __float_as_uint(Ps[rowl0 * 68 + kk + tig]);
            a[1] = __float_as_uint(Ps[rowl1 * 68 + kk + tig]);
            a[2] = __float_as_uint(Ps[rowl0 * 68 + kk + tig + 4]);
            a[3] = __float_as_uint(Ps[rowl1 * 68 + kk + tig + 4]);
#pragma unroll
            for (int nf = 0; nf < 8; nf++) {
                uint32_t b0 = __float_as_uint(Vs[(kk + tig) * 72 + nf * 8 + g]);
                uint32_t b1 = __float_as_uint(Vs[(kk + tig + 4) * 72 + nf * 8 + g]);
                mma8(o[nf], a, b0, b1);
            }
        }
        __syncthreads();
    }

    float inv0 = 1.0f / l0, inv1 = 1.0f / l1;
    const int base0 = ((b * 16 + h) * 2048 + q0 + rowl0) * 64;
    const int base1 = ((b * 16 + h) * 2048 + q0 + rowl1) * 64;
#pragma unroll
    for (int nf = 0; nf < 8; nf++) {
        int col = nf * 8 + 2 * tig;
        float x0 = o[nf][0] * inv0, x1 = o[nf][1] * inv0;
        float y0 = o[nf][2] * inv1, y1 = o[nf][3] * inv1;
        __nv_bfloat162 h0 = __floats2bfloat162_rn(x0, x1);
        __nv_bfloat162 l0p = __floats2bfloat162_rn(x0 - __bfloat162float(h0.x),
                                                   x1 - __bfloat162float(h0.y));
        __nv_bfloat162 h1 = __floats2bfloat162_rn(y0, y1);
        __nv_bfloat162 l1p = __floats2bfloat162_rn(y0 - __bfloat162float(h1.x),
                                                   y1 - __bfloat162float(h1.y));
        *(__nv_bfloat162*)&g_Oh[base0 + col] = h0;
        *(__nv_bfloat162*)&g_Ol[base0 + col] = l0p;
        *(__nv_bfloat162*)&g_Oh[base1 + col] = h1;
        *(__nv_bfloat162*)&g_Ol[base1 + col] = l1p;
    }
}

extern "C" void kernel_launch(void* const* d_in, const int* in_sizes, int n_in,
                              void* d_out, int out_size) {
    const float* q = (const float*)d_in[1];
    const float* k = (const float*)d_in[2];
    const float* v = (const float*)d_in[3];
    const int* mask = (const int*)d_in[4];
    const float* Wq = (const float*)d_in[5];
    const float* Wo = (const float*)d_in[6];
    float* out = (float*)d_out;

    __nv_bfloat16 *ah, *al, *wqh, *wql, *woh, *wol, *oh, *ol;
    cudaGetSymbolAddress((void**)&ah, g_Ah);
    cudaGetSymbolAddress((void**)&al, g_Al);
    cudaGetSymbolAddress((void**)&wqh, g_Wqh);
    cudaGetSymbolAddress((void**)&wql, g_Wql);
    cudaGetSymbolAddress((void**)&woh, g_Woh);
    cudaGetSymbolAddress((void**)&wol, g_Wol);
    cudaGetSymbolAddress((void**)&oh, g_Oh);
    cudaGetSymbolAddress((void**)&ol, g_Ol);

    cudaFuncSetAttribute(attn_kernel, cudaFuncAttributeMaxDynamicSharedMemorySize, ATTN_SMEM);
    cudaFuncSetAttribute(gemm_bf16_kernel<0>, cudaFuncAttributeMaxDynamicSharedMemorySize, GEMM_SMEM);
    cudaFuncSetAttribute(gemm_bf16_kernel<1>, cudaFuncAttributeMaxDynamicSharedMemorySize, GEMM_SMEM);

    mask_reset_kernel<<<1, 1>>>();
    mask_scan_kernel<<<1024, 256>>>((const int4*)mask, PB * PS * PS / 4);

    split_pair_kernel<<<1024, 256>>>(q, ah, al, 4096 * 1024 / 2);
    split_pair_kernel<<<1024, 256>>>(k, ah + 4096 * 1024, al + 4096 * 1024, 4096 * 1024 / 2);
    split_pair_kernel<<<1024, 256>>>(v, ah + 2 * 4096 * 1024, al + 2 * 4096 * 1024, 4096 * 1024 / 2);
    split_pair_kernel<<<512, 256>>>(Wq, wqh, wql, 1024 * 1024 / 2);
    split_pair_kernel<<<512, 256>>>(Wo, woh, wol, 1024 * 1024 / 2);

    gemm_bf16_kernel<0><<<dim3(8, 32, 3), 256, GEMM_SMEM>>>(ah, al, wqh, wql, nullptr);

    attn_kernel<<<dim3(32, 16, 2), 128, ATTN_SMEM>>>(mask);

    gemm_bf16_kernel<1><<<dim3(8, 32, 1), 256, GEMM_SMEM>>>(oh, ol, woh, wol, out);
}